// round 2
// baseline (speedup 1.0000x reference)
#include <cuda_runtime.h>

#define B_ 64
#define T_ 512
#define I_ 2048
#define H_ 128
#define EPS 1e-5f

// ---------------- packed f32x2 helpers (FFMA2: 2 FMAs/instr on sm_10x) --------
__device__ __forceinline__ unsigned long long pack2(float lo, float hi) {
    unsigned long long d;
    asm("mov.b64 %0, {%1,%2};" : "=l"(d) : "f"(lo), "f"(hi));
    return d;
}
__device__ __forceinline__ void unpack2(unsigned long long d, float& lo, float& hi) {
    asm("mov.b64 {%0,%1}, %2;" : "=f"(lo), "=f"(hi) : "l"(d));
}
__device__ __forceinline__ unsigned long long ffma2(unsigned long long a,
                                                    unsigned long long b,
                                                    unsigned long long c) {
    unsigned long long d;
    asm("fma.rn.f32x2 %0, %1, %2, %3;" : "=l"(d) : "l"(a), "l"(b), "l"(c));
    return d;
}

// scratch: xp = x @ W_ih^T + b_ih, [B, T, H] fp32 (16 MB, L2-resident)
__device__ float g_xp[B_ * T_ * H_];

// =============================================================================
// Kernel 1: xp GEMM.  M = B*T = 32768, N = H = 128, K = I = 2048.
// A = x (row-major M x K), B = W_ih (row-major N x K)  ->  C = A * B^T.
// 128x128 block tile, BK=16, 256 threads, 8x8 micro-tile via FFMA2.
// =============================================================================
#define BM 128
#define BN 128
#define BK 16

__global__ __launch_bounds__(256, 2) void xp_gemm(const float* __restrict__ x,
                                                  const float* __restrict__ W,
                                                  const float* __restrict__ bias) {
    __shared__ float As[BK][BM];
    __shared__ float Bs[BK][BN];

    const int tid = threadIdx.x;
    const int m0  = blockIdx.x * BM;
    const int tm8 = (tid >> 4) * 8;   // 16 thread-rows
    const int tn8 = (tid & 15) * 8;   // 16 thread-cols

    unsigned long long acc[8][4];
#pragma unroll
    for (int i = 0; i < 8; i++)
#pragma unroll
        for (int j = 0; j < 4; j++) acc[i][j] = 0ull;

    // loader coords: 512 float4 slots per tile, 2 per thread
    const int r0 = tid >> 2,         c40 = tid & 3;
    const int r1 = (tid + 256) >> 2, c41 = (tid + 256) & 3;

    // preload tile 0
    float4 a0r = *(const float4*)(x + (size_t)(m0 + r0) * I_ + c40 * 4);
    float4 a1r = *(const float4*)(x + (size_t)(m0 + r1) * I_ + c41 * 4);
    float4 b0r = *(const float4*)(W + (size_t)r0 * I_ + c40 * 4);
    float4 b1r = *(const float4*)(W + (size_t)r1 * I_ + c41 * 4);

    const int NKT = I_ / BK;  // 128
    for (int kt = 0; kt < NKT; kt++) {
        // commit prefetched regs to smem
        As[c40 * 4 + 0][r0] = a0r.x; As[c40 * 4 + 1][r0] = a0r.y;
        As[c40 * 4 + 2][r0] = a0r.z; As[c40 * 4 + 3][r0] = a0r.w;
        As[c41 * 4 + 0][r1] = a1r.x; As[c41 * 4 + 1][r1] = a1r.y;
        As[c41 * 4 + 2][r1] = a1r.z; As[c41 * 4 + 3][r1] = a1r.w;
        Bs[c40 * 4 + 0][r0] = b0r.x; Bs[c40 * 4 + 1][r0] = b0r.y;
        Bs[c40 * 4 + 2][r0] = b0r.z; Bs[c40 * 4 + 3][r0] = b0r.w;
        Bs[c41 * 4 + 0][r1] = b1r.x; Bs[c41 * 4 + 1][r1] = b1r.y;
        Bs[c41 * 4 + 2][r1] = b1r.z; Bs[c41 * 4 + 3][r1] = b1r.w;
        __syncthreads();

        // prefetch next tile (hides DRAM/L2 latency behind compute)
        if (kt + 1 < NKT) {
            const int kb = (kt + 1) * BK;
            a0r = *(const float4*)(x + (size_t)(m0 + r0) * I_ + kb + c40 * 4);
            a1r = *(const float4*)(x + (size_t)(m0 + r1) * I_ + kb + c41 * 4);
            b0r = *(const float4*)(W + (size_t)r0 * I_ + kb + c40 * 4);
            b1r = *(const float4*)(W + (size_t)r1 * I_ + kb + c41 * 4);
        }

#pragma unroll
        for (int k = 0; k < BK; k++) {
            const float4 a0 = *(const float4*)&As[k][tm8];
            const float4 a1 = *(const float4*)&As[k][tm8 + 4];
            const unsigned long long* Bp = (const unsigned long long*)&Bs[k][tn8];
            const unsigned long long bv0 = Bp[0], bv1 = Bp[1];
            const unsigned long long bv2 = Bp[2], bv3 = Bp[3];

            unsigned long long ad;
            ad = pack2(a0.x, a0.x);
            acc[0][0] = ffma2(ad, bv0, acc[0][0]); acc[0][1] = ffma2(ad, bv1, acc[0][1]);
            acc[0][2] = ffma2(ad, bv2, acc[0][2]); acc[0][3] = ffma2(ad, bv3, acc[0][3]);
            ad = pack2(a0.y, a0.y);
            acc[1][0] = ffma2(ad, bv0, acc[1][0]); acc[1][1] = ffma2(ad, bv1, acc[1][1]);
            acc[1][2] = ffma2(ad, bv2, acc[1][2]); acc[1][3] = ffma2(ad, bv3, acc[1][3]);
            ad = pack2(a0.z, a0.z);
            acc[2][0] = ffma2(ad, bv0, acc[2][0]); acc[2][1] = ffma2(ad, bv1, acc[2][1]);
            acc[2][2] = ffma2(ad, bv2, acc[2][2]); acc[2][3] = ffma2(ad, bv3, acc[2][3]);
            ad = pack2(a0.w, a0.w);
            acc[3][0] = ffma2(ad, bv0, acc[3][0]); acc[3][1] = ffma2(ad, bv1, acc[3][1]);
            acc[3][2] = ffma2(ad, bv2, acc[3][2]); acc[3][3] = ffma2(ad, bv3, acc[3][3]);
            ad = pack2(a1.x, a1.x);
            acc[4][0] = ffma2(ad, bv0, acc[4][0]); acc[4][1] = ffma2(ad, bv1, acc[4][1]);
            acc[4][2] = ffma2(ad, bv2, acc[4][2]); acc[4][3] = ffma2(ad, bv3, acc[4][3]);
            ad = pack2(a1.y, a1.y);
            acc[5][0] = ffma2(ad, bv0, acc[5][0]); acc[5][1] = ffma2(ad, bv1, acc[5][1]);
            acc[5][2] = ffma2(ad, bv2, acc[5][2]); acc[5][3] = ffma2(ad, bv3, acc[5][3]);
            ad = pack2(a1.z, a1.z);
            acc[6][0] = ffma2(ad, bv0, acc[6][0]); acc[6][1] = ffma2(ad, bv1, acc[6][1]);
            acc[6][2] = ffma2(ad, bv2, acc[6][2]); acc[6][3] = ffma2(ad, bv3, acc[6][3]);
            ad = pack2(a1.w, a1.w);
            acc[7][0] = ffma2(ad, bv0, acc[7][0]); acc[7][1] = ffma2(ad, bv1, acc[7][1]);
            acc[7][2] = ffma2(ad, bv2, acc[7][2]); acc[7][3] = ffma2(ad, bv3, acc[7][3]);
        }
        __syncthreads();
    }

    // epilogue: + bias, float2 stores
#pragma unroll
    for (int j = 0; j < 4; j++) {
        const float blo = bias[tn8 + 2 * j];
        const float bhi = bias[tn8 + 2 * j + 1];
#pragma unroll
        for (int i = 0; i < 8; i++) {
            float lo, hi;
            unpack2(acc[i][j], lo, hi);
            *(float2*)&g_xp[(size_t)(m0 + tm8 + i) * H_ + tn8 + 2 * j] =
                make_float2(lo + blo, hi + bhi);
        }
    }
}

// =============================================================================
// Kernel 2: per-batch recurrence + FC tail + LayerNorm.
// 64 blocks (one per batch chain), 128 threads (thread j owns output unit j).
// W_hh row j lives in 64 packed-u64 registers; h double-buffered in SMEM;
// one __syncthreads per step. tanh via ex2+rcp (abs err ~1e-6).
// =============================================================================
__global__ __launch_bounds__(128, 1) void rnn_tail(
    const float* __restrict__ W_hh, const float* __restrict__ b_hh,
    const float* __restrict__ W1, const float* __restrict__ b1,
    const float* __restrict__ W2, const float* __restrict__ b2,
    const float* __restrict__ gamma, const float* __restrict__ beta,
    float* __restrict__ out) {
    const int b = blockIdx.x;
    const int j = threadIdx.x;

    __shared__ __align__(16) float hbuf[2][H_];
    __shared__ float red[4];

    // W_hh row j -> registers (64 x u64 = 128 fp32)
    unsigned long long w2[64];
    const unsigned long long* wrow = (const unsigned long long*)(W_hh + j * H_);
#pragma unroll
    for (int kk = 0; kk < 64; kk++) w2[kk] = wrow[kk];
    const float bh = b_hh[j];

    hbuf[0][j] = 0.0f;
    const float* xpb = g_xp + (size_t)b * T_ * H_ + j;
    float x0 = xpb[0];
    float x1 = xpb[H_];
    __syncthreads();

    int p = 0;
    for (int t = 0; t < T_; t++) {
        const float xt = x0;
        x0 = x1;
        // branchless depth-2 prefetch (clamped index; harmless re-read at tail)
        const int tpre = (t + 2 < T_) ? (t + 2) : (T_ - 1);
        x1 = xpb[(size_t)tpre * H_];

        const unsigned long long* h2 = (const unsigned long long*)hbuf[p];
        unsigned long long acc0 = 0ull, acc1 = 0ull;
#pragma unroll
        for (int kk = 0; kk < 64; kk += 2) {
            acc0 = ffma2(w2[kk], h2[kk], acc0);
            acc1 = ffma2(w2[kk + 1], h2[kk + 1], acc1);
        }
        float l0, h0v, l1, h1v;
        unpack2(acc0, l0, h0v);
        unpack2(acc1, l1, h1v);
        const float s = ((l0 + h0v) + (l1 + h1v)) + xt + bh;

        // tanh(s) = 1 - 2/(1 + e^{2s}) via MUFU ex2 + rcp
        float e;
        asm("ex2.approx.f32 %0, %1;" : "=f"(e) : "f"(s * 2.8853900817779268f));
        float r;
        asm("rcp.approx.f32 %0, %1;" : "=f"(r) : "f"(e + 1.0f));
        hbuf[p ^ 1][j] = fmaf(-2.0f, r, 1.0f);
        __syncthreads();
        p ^= 1;
    }

    // ---- z1 = relu(hT @ W1^T + b1) ----
    float z1;
    {
        const unsigned long long* wr = (const unsigned long long*)(W1 + j * H_);
        const unsigned long long* hv = (const unsigned long long*)hbuf[p];
        unsigned long long a0 = 0ull, a1 = 0ull;
#pragma unroll
        for (int kk = 0; kk < 64; kk += 2) {
            a0 = ffma2(wr[kk], hv[kk], a0);
            a1 = ffma2(wr[kk + 1], hv[kk + 1], a1);
        }
        float l0, hh0, l1, hh1;
        unpack2(a0, l0, hh0);
        unpack2(a1, l1, hh1);
        z1 = fmaxf((l0 + hh0) + (l1 + hh1) + b1[j], 0.0f);
    }
    hbuf[p ^ 1][j] = z1;
    __syncthreads();

    // ---- z2 = relu(z1 @ W2^T + b2) ----
    float z2;
    {
        const unsigned long long* wr = (const unsigned long long*)(W2 + j * H_);
        const unsigned long long* hv = (const unsigned long long*)hbuf[p ^ 1];
        unsigned long long a0 = 0ull, a1 = 0ull;
#pragma unroll
        for (int kk = 0; kk < 64; kk += 2) {
            a0 = ffma2(wr[kk], hv[kk], a0);
            a1 = ffma2(wr[kk + 1], hv[kk + 1], a1);
        }
        float l0, hh0, l1, hh1;
        unpack2(a0, l0, hh0);
        unpack2(a1, l1, hh1);
        z2 = fmaxf((l0 + hh0) + (l1 + hh1) + b2[j], 0.0f);
    }

    // ---- LayerNorm over the 128 units ----
    float sum = z2;
#pragma unroll
    for (int o = 16; o; o >>= 1) sum += __shfl_xor_sync(0xffffffffu, sum, o);
    if ((j & 31) == 0) red[j >> 5] = sum;
    __syncthreads();
    const float mu = (red[0] + red[1] + red[2] + red[3]) * (1.0f / H_);
    const float d = z2 - mu;
    float sq = d * d;
    __syncthreads();  // protect red[] before reuse
#pragma unroll
    for (int o = 16; o; o >>= 1) sq += __shfl_xor_sync(0xffffffffu, sq, o);
    if ((j & 31) == 0) red[j >> 5] = sq;
    __syncthreads();
    const float var = (red[0] + red[1] + red[2] + red[3]) * (1.0f / H_);

    out[b * H_ + j] = gamma[j] * d * rsqrtf(var + EPS) + beta[j];
}

// =============================================================================
extern "C" void kernel_launch(void* const* d_in, const int* in_sizes, int n_in,
                              void* d_out, int out_size) {
    const float* x     = (const float*)d_in[0];
    const float* W_ih  = (const float*)d_in[1];
    const float* b_ih  = (const float*)d_in[2];
    const float* W_hh  = (const float*)d_in[3];
    const float* b_hh  = (const float*)d_in[4];
    const float* W1    = (const float*)d_in[5];
    const float* b1    = (const float*)d_in[6];
    const float* W2    = (const float*)d_in[7];
    const float* b2    = (const float*)d_in[8];
    const float* gamma = (const float*)d_in[9];
    const float* beta  = (const float*)d_in[10];
    float* out = (float*)d_out;

    xp_gemm<<<(B_ * T_) / BM, 256>>>(x, W_ih, b_ih);
    rnn_tail<<<B_, H_>>>(W_hh, b_hh, W1, b1, W2, b2, gamma, beta, out);
}

// round 9
// speedup vs baseline: 1.3812x; 1.3812x over previous
#include <cuda_runtime.h>
#include <cuda_bf16.h>
#include <cstdint>

#define B_ 64
#define T_ 512
#define I_ 2048
#define H_ 128
#define EPS 1e-5f

// ---------------- packed f32x2 helpers (validated on this build in R2) -------
__device__ __forceinline__ unsigned long long pack2(float lo, float hi) {
    unsigned long long d;
    asm("mov.b64 %0, {%1,%2};" : "=l"(d) : "f"(lo), "f"(hi));
    return d;
}
__device__ __forceinline__ void unpack2(unsigned long long d, float& lo, float& hi) {
    asm("mov.b64 {%0,%1}, %2;" : "=f"(lo), "=f"(hi) : "l"(d));
}
__device__ __forceinline__ unsigned long long ffma2(unsigned long long a,
                                                    unsigned long long b,
                                                    unsigned long long c) {
    unsigned long long d;
    asm("fma.rn.f32x2 %0, %1, %2, %3;" : "=l"(d) : "l"(a), "l"(b), "l"(c));
    return d;
}
__device__ __forceinline__ uint32_t smem_to_u32(const void* p) {
    uint32_t a;
    asm("{ .reg .u64 t; cvta.to.shared.u64 t, %1; cvt.u32.u64 %0, t; }"
        : "=r"(a) : "l"(p));
    return a;
}

// ---------------- sm_80-level tensor ops (NO 'a'-suffix features) ------------
#define LDSM4(r, addr)                                                          \
    asm volatile("ldmatrix.sync.aligned.m8n8.x4.shared.b16 {%0,%1,%2,%3}, [%4];" \
                 : "=r"((r)[0]), "=r"((r)[1]), "=r"((r)[2]), "=r"((r)[3])       \
                 : "r"(addr))

#define MMA16816(d, a, b0, b1)                                                  \
    asm volatile("mma.sync.aligned.m16n8k16.row.col.f32.bf16.bf16.f32 "         \
                 "{%0,%1,%2,%3}, {%4,%5,%6,%7}, {%8,%9}, {%0,%1,%2,%3};"        \
                 : "+f"((d)[0]), "+f"((d)[1]), "+f"((d)[2]), "+f"((d)[3])       \
                 : "r"((a)[0]), "r"((a)[1]), "r"((a)[2]), "r"((a)[3]),          \
                   "r"(b0), "r"(b1))

// =============================== globals =====================================
__device__ float g_xp[B_ * T_ * H_];                 // xp (no bias), 16 MB
__device__ __nv_bfloat16 g_w_hi[H_ * I_];            // W_ih split hi
__device__ __nv_bfloat16 g_w_lo[H_ * I_];            // W_ih split lo

// =============================================================================
// Kernel 0: split W_ih fp32 -> bf16 hi/lo
// =============================================================================
__global__ void w_cvt(const float* __restrict__ W) {
    int i = blockIdx.x * blockDim.x + threadIdx.x;
    const int N = H_ * I_;
    for (; i < N; i += gridDim.x * blockDim.x) {
        float v = W[i];
        __nv_bfloat16 h = __float2bfloat16_rn(v);
        float fh = __bfloat162float(h);
        g_w_hi[i] = h;
        g_w_lo[i] = __float2bfloat16_rn(v - fh);
    }
}

// =============================================================================
// Kernel 1: xp = x @ W_ih^T via mma.sync bf16 hi/lo split (3 terms, fp32 acc).
// 256 CTAs x 256 threads. 128x128 tile, BK=32, double-buffered smem.
// Warp grid 4x2 -> 32x64 per warp. ldmatrix from 80B-padded rows.
// =============================================================================
#define BK 32
#define RSB 80                      // bytes per padded row (32 bf16 data + pad)
#define MAT_B (128 * RSB)           // 10240 B per matrix half
#define STG (4 * MAT_B)             // Ah, Al, Bh, Bl
#define SMT (2 * STG)               // 81920 B

__global__ __launch_bounds__(256, 1) void xp_gemm_mma(const float* __restrict__ x) {
    extern __shared__ __align__(16) char sm[];
    const uint32_t sb = smem_to_u32(sm);
    const int tid = threadIdx.x;
    const int wid = tid >> 5, lane = tid & 31;
    const int wm = wid >> 1, wn = wid & 1;     // 4x2 warp grid
    const int m0 = blockIdx.x * 128;

    float d[2][8][4];
#pragma unroll
    for (int i = 0; i < 2; i++)
#pragma unroll
        for (int j = 0; j < 8; j++)
#pragma unroll
            for (int k = 0; k < 4; k++) d[i][j][k] = 0.0f;

    // loader coords
    const int ar = tid >> 3, akq = tid & 7;    // A: 8 float4 per row of 32 floats
    float4 av[4];
    uint4 bv[4];

    const int NKT = I_ / BK;  // 64

    // ---- gmem fetch of chunk kt into regs ----
#define FETCH(kt)                                                                   \
    do {                                                                            \
        const int k0f = (kt) * BK;                                                  \
        _Pragma("unroll") for (int j = 0; j < 4; j++) {                             \
            const int f = tid + 256 * j;                                            \
            av[j] = *(const float4*)(x + (size_t)(m0 + (f >> 3)) * I_ + k0f + (f & 7) * 4); \
        }                                                                           \
        _Pragma("unroll") for (int j = 0; j < 4; j++) {                             \
            const int idx = tid + 256 * j;                                          \
            const int half = idx >> 9, f = idx & 511;                               \
            const __nv_bfloat16* src = (half ? g_w_lo : g_w_hi);                    \
            bv[j] = *(const uint4*)(src + (size_t)(f >> 2) * I_ + k0f + (f & 3) * 8); \
        }                                                                           \
    } while (0)

    // ---- commit regs to smem stage s (convert A to bf16 hi/lo) ----
#define STS(s)                                                                      \
    do {                                                                            \
        _Pragma("unroll") for (int j = 0; j < 4; j++) {                             \
            const int f = tid + 256 * j;                                            \
            const int row = f >> 3, kq = f & 7;                                     \
            const float4 v = av[j];                                                 \
            uint32_t h01, h23, l01, l23;                                            \
            asm("cvt.rn.bf16x2.f32 %0, %1, %2;" : "=r"(h01) : "f"(v.y), "f"(v.x));  \
            asm("cvt.rn.bf16x2.f32 %0, %1, %2;" : "=r"(h23) : "f"(v.w), "f"(v.z));  \
            const float f0 = __uint_as_float(h01 << 16);                            \
            const float f1 = __uint_as_float(h01 & 0xffff0000u);                    \
            const float f2 = __uint_as_float(h23 << 16);                            \
            const float f3 = __uint_as_float(h23 & 0xffff0000u);                    \
            asm("cvt.rn.bf16x2.f32 %0, %1, %2;" : "=r"(l01) : "f"(v.y - f1), "f"(v.x - f0)); \
            asm("cvt.rn.bf16x2.f32 %0, %1, %2;" : "=r"(l23) : "f"(v.w - f3), "f"(v.z - f2)); \
            char* base = sm + (s) * STG + row * RSB + kq * 8;                       \
            *(uint2*)(base) = make_uint2(h01, h23);                                 \
            *(uint2*)(base + MAT_B) = make_uint2(l01, l23);                         \
        }                                                                           \
        _Pragma("unroll") for (int j = 0; j < 4; j++) {                             \
            const int idx = tid + 256 * j;                                          \
            const int half = idx >> 9, f = idx & 511;                               \
            *(uint4*)(sm + (s) * STG + (2 + half) * MAT_B + (f >> 2) * RSB + (f & 3) * 16) = bv[j]; \
        }                                                                           \
    } while (0)

    FETCH(0);
    STS(0);
    __syncthreads();

    const int lr = lane & 15, lc = lane >> 4;

    for (int kt = 0; kt < NKT; kt++) {
        const int s = kt & 1;
        if (kt + 1 < NKT) FETCH(kt + 1);

        const uint32_t aBh = sb + s * STG;
        const uint32_t bBh = aBh + 2 * MAT_B;
#pragma unroll
        for (int k16 = 0; k16 < 2; k16++) {
            const uint32_t ko = k16 * 32;  // 16 bf16 = 32 B
            uint32_t aH[2][4], aL[2][4], bH[4][4], bL[4][4];
#pragma unroll
            for (int mt = 0; mt < 2; mt++) {
                const uint32_t ad = aBh + (wm * 32 + mt * 16 + lr) * RSB + ko + lc * 16;
                LDSM4(aH[mt], ad);
                LDSM4(aL[mt], ad + MAT_B);
            }
#pragma unroll
            for (int np = 0; np < 4; np++) {
                const uint32_t bd = bBh + (wn * 64 + np * 16 + lr) * RSB + ko + lc * 16;
                LDSM4(bH[np], bd);
                LDSM4(bL[np], bd + MAT_B);
            }
#pragma unroll
            for (int mt = 0; mt < 2; mt++) {
#pragma unroll
                for (int nt = 0; nt < 8; nt++) {
                    const int np = nt >> 1, wh = nt & 1;
                    const uint32_t bh0 = wh ? bH[np][1] : bH[np][0];
                    const uint32_t bh1 = wh ? bH[np][3] : bH[np][2];
                    const uint32_t bl0 = wh ? bL[np][1] : bL[np][0];
                    const uint32_t bl1 = wh ? bL[np][3] : bL[np][2];
                    MMA16816(d[mt][nt], aH[mt], bh0, bh1);  // Ah*Bh
                    MMA16816(d[mt][nt], aH[mt], bl0, bl1);  // Ah*Bl
                    MMA16816(d[mt][nt], aL[mt], bh0, bh1);  // Al*Bh
                }
            }
        }

        if (kt + 1 < NKT) {
            __syncthreads();   // all warps done reading stage s^1 (prev iter)
            STS(s ^ 1);
            __syncthreads();   // stage s^1 visible for next iter
        }
    }

    // ---- epilogue: c-frags -> g_xp (raw product; bias folded downstream) ----
    const int er = lane >> 2, ec = (lane & 3) * 2;
#pragma unroll
    for (int mt = 0; mt < 2; mt++) {
#pragma unroll
        for (int nt = 0; nt < 8; nt++) {
            const int grow = m0 + wm * 32 + mt * 16 + er;
            const int gcol = wn * 64 + nt * 8 + ec;
            *(float2*)&g_xp[(size_t)grow * H_ + gcol] = make_float2(d[mt][nt][0], d[mt][nt][1]);
            *(float2*)&g_xp[(size_t)(grow + 8) * H_ + gcol] = make_float2(d[mt][nt][2], d[mt][nt][3]);
        }
    }
#undef FETCH
#undef STS
}

// =============================================================================
// Kernel 2: per-batch recurrence + FC tail + LayerNorm.
// 64 blocks x 128 threads. 4 accumulator chains (depth 16), LDS.128 h loads.
// b_ih folded in here (GEMM stores raw product).
// =============================================================================
__global__ __launch_bounds__(128, 1) void rnn_tail(
    const float* __restrict__ b_ih,
    const float* __restrict__ W_hh, const float* __restrict__ b_hh,
    const float* __restrict__ W1, const float* __restrict__ b1,
    const float* __restrict__ W2, const float* __restrict__ b2,
    const float* __restrict__ gamma, const float* __restrict__ beta,
    float* __restrict__ out) {
    const int b = blockIdx.x;
    const int j = threadIdx.x;

    __shared__ __align__(16) float hbuf[2][H_];
    __shared__ float red[4];

    unsigned long long w2[64];
    const unsigned long long* wrow = (const unsigned long long*)(W_hh + j * H_);
#pragma unroll
    for (int kk = 0; kk < 64; kk++) w2[kk] = wrow[kk];
    const float bh = b_hh[j] + b_ih[j];  // fold input-proj bias

    hbuf[0][j] = 0.0f;
    const float* xpb = g_xp + (size_t)b * T_ * H_ + j;
    float x0 = xpb[0];
    float x1 = xpb[H_];
    __syncthreads();

    int p = 0;
    for (int t = 0; t < T_; t++) {
        const float xt = x0;
        x0 = x1;
        const int tpre = (t + 2 < T_) ? (t + 2) : (T_ - 1);
        x1 = xpb[(size_t)tpre * H_];

        const float* hb = hbuf[p];
        unsigned long long a0 = 0ull, a1 = 0ull, a2 = 0ull, a3 = 0ull;
#pragma unroll
        for (int kk = 0; kk < 32; kk += 2) {
            const float4 hA = *(const float4*)(hb + 4 * kk);
            const float4 hB = *(const float4*)(hb + 4 * kk + 4);
            a0 = ffma2(w2[2 * kk + 0], pack2(hA.x, hA.y), a0);
            a1 = ffma2(w2[2 * kk + 1], pack2(hA.z, hA.w), a1);
            a2 = ffma2(w2[2 * kk + 2], pack2(hB.x, hB.y), a2);
            a3 = ffma2(w2[2 * kk + 3], pack2(hB.z, hB.w), a3);
        }
        float s0, s1, s2, s3, s4, s5, s6, s7;
        unpack2(a0, s0, s1); unpack2(a1, s2, s3);
        unpack2(a2, s4, s5); unpack2(a3, s6, s7);
        const float s = (((s0 + s1) + (s2 + s3)) + ((s4 + s5) + (s6 + s7))) + xt + bh;

        // tanh(s) = 1 - 2/(1 + e^{2s}) via MUFU ex2 + rcp
        float e;
        asm("ex2.approx.f32 %0, %1;" : "=f"(e) : "f"(s * 2.8853900817779268f));
        float r;
        asm("rcp.approx.f32 %0, %1;" : "=f"(r) : "f"(e + 1.0f));
        hbuf[p ^ 1][j] = fmaf(-2.0f, r, 1.0f);
        __syncthreads();
        p ^= 1;
    }

    // ---- z1 = relu(hT @ W1^T + b1) ----
    float z1;
    {
        const unsigned long long* wr = (const unsigned long long*)(W1 + j * H_);
        const unsigned long long* hv = (const unsigned long long*)hbuf[p];
        unsigned long long a0 = 0ull, a1 = 0ull;
#pragma unroll
        for (int kk = 0; kk < 64; kk += 2) {
            a0 = ffma2(wr[kk], hv[kk], a0);
            a1 = ffma2(wr[kk + 1], hv[kk + 1], a1);
        }
        float l0, hh0, l1, hh1;
        unpack2(a0, l0, hh0); unpack2(a1, l1, hh1);
        z1 = fmaxf((l0 + hh0) + (l1 + hh1) + b1[j], 0.0f);
    }
    hbuf[p ^ 1][j] = z1;
    __syncthreads();

    // ---- z2 = relu(z1 @ W2^T + b2) ----
    float z2;
    {
        const unsigned long long* wr = (const unsigned long long*)(W2 + j * H_);
        const unsigned long long* hv = (const unsigned long long*)hbuf[p ^ 1];
        unsigned long long a0 = 0ull, a1 = 0ull;
#pragma unroll
        for (int kk = 0; kk < 64; kk += 2) {
            a0 = ffma2(wr[kk], hv[kk], a0);
            a1 = ffma2(wr[kk + 1], hv[kk + 1], a1);
        }
        float l0, hh0, l1, hh1;
        unpack2(a0, l0, hh0); unpack2(a1, l1, hh1);
        z2 = fmaxf((l0 + hh0) + (l1 + hh1) + b2[j], 0.0f);
    }

    // ---- LayerNorm ----
    float sum = z2;
#pragma unroll
    for (int o = 16; o; o >>= 1) sum += __shfl_xor_sync(0xffffffffu, sum, o);
    if ((j & 31) == 0) red[j >> 5] = sum;
    __syncthreads();
    const float mu = (red[0] + red[1] + red[2] + red[3]) * (1.0f / H_);
    const float dd = z2 - mu;
    float sq = dd * dd;
    __syncthreads();
#pragma unroll
    for (int o = 16; o; o >>= 1) sq += __shfl_xor_sync(0xffffffffu, sq, o);
    if ((j & 31) == 0) red[j >> 5] = sq;
    __syncthreads();
    const float var = (red[0] + red[1] + red[2] + red[3]) * (1.0f / H_);

    out[b * H_ + j] = gamma[j] * dd * rsqrtf(var + EPS) + beta[j];
}

// =============================================================================
extern "C" void kernel_launch(void* const* d_in, const int* in_sizes, int n_in,
                              void* d_out, int out_size) {
    const float* x     = (const float*)d_in[0];
    const float* W_ih  = (const float*)d_in[1];
    const float* b_ih  = (const float*)d_in[2];
    const float* W_hh  = (const float*)d_in[3];
    const float* b_hh  = (const float*)d_in[4];
    const float* W1    = (const float*)d_in[5];
    const float* b1    = (const float*)d_in[6];
    const float* W2    = (const float*)d_in[7];
    const float* b2    = (const float*)d_in[8];
    const float* gamma = (const float*)d_in[9];
    const float* beta  = (const float*)d_in[10];
    float* out = (float*)d_out;

    cudaFuncSetAttribute(xp_gemm_mma, cudaFuncAttributeMaxDynamicSharedMemorySize, SMT);

    w_cvt<<<64, 256>>>(W_ih);
    xp_gemm_mma<<<(B_ * T_) / 128, 256, SMT>>>(x);
    rnn_tail<<<B_, H_>>>(b_ih, W_hh, b_hh, W1, b1, W2, b2, gamma, beta, out);
}

// round 14
// speedup vs baseline: 1.3867x; 1.0040x over previous
#include <cuda_runtime.h>
#include <cuda_bf16.h>
#include <cstdint>

#define B_ 64
#define T_ 512
#define I_ 2048
#define H_ 128
#define EPS 1e-5f

// ---------------- packed f32x2 helpers ---------------------------------------
__device__ __forceinline__ unsigned long long pack2(float lo, float hi) {
    unsigned long long d;
    asm("mov.b64 %0, {%1,%2};" : "=l"(d) : "f"(lo), "f"(hi));
    return d;
}
__device__ __forceinline__ void unpack2(unsigned long long d, float& lo, float& hi) {
    asm("mov.b64 {%0,%1}, %2;" : "=f"(lo), "=f"(hi) : "l"(d));
}
__device__ __forceinline__ unsigned long long ffma2(unsigned long long a,
                                                    unsigned long long b,
                                                    unsigned long long c) {
    unsigned long long d;
    asm("fma.rn.f32x2 %0, %1, %2, %3;" : "=l"(d) : "l"(a), "l"(b), "l"(c));
    return d;
}
__device__ __forceinline__ uint32_t smem_to_u32(const void* p) {
    uint32_t a;
    asm("{ .reg .u64 t; cvta.to.shared.u64 t, %1; cvt.u32.u64 %0, t; }"
        : "=r"(a) : "l"(p));
    return a;
}

// ---------------- sm_80-level tensor ops -------------------------------------
#define LDSM4(r, addr)                                                          \
    asm volatile("ldmatrix.sync.aligned.m8n8.x4.shared.b16 {%0,%1,%2,%3}, [%4];" \
                 : "=r"((r)[0]), "=r"((r)[1]), "=r"((r)[2]), "=r"((r)[3])       \
                 : "r"(addr))

#define MMA16816(d, a, b0, b1)                                                  \
    asm volatile("mma.sync.aligned.m16n8k16.row.col.f32.bf16.bf16.f32 "         \
                 "{%0,%1,%2,%3}, {%4,%5,%6,%7}, {%8,%9}, {%0,%1,%2,%3};"        \
                 : "+f"((d)[0]), "+f"((d)[1]), "+f"((d)[2]), "+f"((d)[3])       \
                 : "r"((a)[0]), "r"((a)[1]), "r"((a)[2]), "r"((a)[3]),          \
                   "r"(b0), "r"(b1))

#define CP_COMMIT() asm volatile("cp.async.commit_group;" ::: "memory")
#define CP_WAIT1()  asm volatile("cp.async.wait_group 1;" ::: "memory")

// =============================== globals =====================================
__device__ float g_xp[B_ * T_ * H_];                 // xp (no bias), 16 MB
__device__ __nv_bfloat16 g_w_hi[H_ * I_];            // W_ih split hi
__device__ __nv_bfloat16 g_w_lo[H_ * I_];            // W_ih split lo

// =============================================================================
// Kernel 0: split W_ih fp32 -> bf16 hi/lo (256 blocks, float4: ~3us)
// =============================================================================
__global__ void w_cvt(const float* __restrict__ W) {
    const int i4 = blockIdx.x * blockDim.x + threadIdx.x;   // 65536 threads
    const float4 v = *(const float4*)(W + i4 * 4);
    uint32_t h01, h23;
    asm("cvt.rn.bf16x2.f32 %0, %1, %2;" : "=r"(h01) : "f"(v.y), "f"(v.x));
    asm("cvt.rn.bf16x2.f32 %0, %1, %2;" : "=r"(h23) : "f"(v.w), "f"(v.z));
    const float f0 = __uint_as_float(h01 << 16);
    const float f1 = __uint_as_float(h01 & 0xffff0000u);
    const float f2 = __uint_as_float(h23 << 16);
    const float f3 = __uint_as_float(h23 & 0xffff0000u);
    uint32_t l01, l23;
    asm("cvt.rn.bf16x2.f32 %0, %1, %2;" : "=r"(l01) : "f"(v.y - f1), "f"(v.x - f0));
    asm("cvt.rn.bf16x2.f32 %0, %1, %2;" : "=r"(l23) : "f"(v.w - f3), "f"(v.z - f2));
    *(uint2*)(g_w_hi + i4 * 4) = make_uint2(h01, h23);
    *(uint2*)(g_w_lo + i4 * 4) = make_uint2(l01, l23);
}

// =============================================================================
// Kernel 1: xp = x @ W_ih^T via mma.sync bf16 hi/lo split (3 terms, fp32 acc).
// BK=64, XOR-8 swizzled 128B rows, cp.async for W halves, double-buffered.
// 256 CTAs x 256 threads; warp grid 4x2 (32x64 per warp).
// =============================================================================
#define NKT (I_ / 64)            // 32
#define MATB (128 * 128)         // 16 KB per matrix (128 rows x 128B)
#define STGB (4 * MATB)          // Ah, Al, Bh, Bl = 64 KB
#define SMTB (2 * STGB)          // 128 KB

__device__ __forceinline__ void cpb(uint32_t sbstage, int tid, int kt) {
#pragma unroll
    for (int j = 0; j < 8; j++) {
        const int idx = tid + 256 * j;
        const int half = idx >> 10;
        const int row = (idx >> 3) & 127;
        const int c = idx & 7;
        const __nv_bfloat16* src =
            (half ? g_w_lo : g_w_hi) + (size_t)row * I_ + kt * 64 + c * 8;
        const uint32_t dst = sbstage + (2 + half) * MATB + row * 128 + ((c ^ (row & 7)) * 16);
        asm volatile("cp.async.cg.shared.global [%0], [%1], 16;" :: "r"(dst), "l"(src));
    }
}

__device__ __forceinline__ void sts_a(char* smbase, const float4* av, int ar, int ah) {
#pragma unroll
    for (int q = 0; q < 4; q++) {
        const float4 v0 = av[2 * q], v1 = av[2 * q + 1];
        uint32_t h0, h1, h2, h3, l0, l1, l2, l3;
        asm("cvt.rn.bf16x2.f32 %0, %1, %2;" : "=r"(h0) : "f"(v0.y), "f"(v0.x));
        asm("cvt.rn.bf16x2.f32 %0, %1, %2;" : "=r"(h1) : "f"(v0.w), "f"(v0.z));
        asm("cvt.rn.bf16x2.f32 %0, %1, %2;" : "=r"(h2) : "f"(v1.y), "f"(v1.x));
        asm("cvt.rn.bf16x2.f32 %0, %1, %2;" : "=r"(h3) : "f"(v1.w), "f"(v1.z));
        const float f0 = __uint_as_float(h0 << 16), f1 = __uint_as_float(h0 & 0xffff0000u);
        const float f2 = __uint_as_float(h1 << 16), f3 = __uint_as_float(h1 & 0xffff0000u);
        const float f4 = __uint_as_float(h2 << 16), f5 = __uint_as_float(h2 & 0xffff0000u);
        const float f6 = __uint_as_float(h3 << 16), f7 = __uint_as_float(h3 & 0xffff0000u);
        asm("cvt.rn.bf16x2.f32 %0, %1, %2;" : "=r"(l0) : "f"(v0.y - f1), "f"(v0.x - f0));
        asm("cvt.rn.bf16x2.f32 %0, %1, %2;" : "=r"(l1) : "f"(v0.w - f3), "f"(v0.z - f2));
        asm("cvt.rn.bf16x2.f32 %0, %1, %2;" : "=r"(l2) : "f"(v1.y - f5), "f"(v1.x - f4));
        asm("cvt.rn.bf16x2.f32 %0, %1, %2;" : "=r"(l3) : "f"(v1.w - f7), "f"(v1.z - f6));
        const int c16 = ah * 4 + q;
        const int off = ar * 128 + ((c16 ^ (ar & 7)) * 16);
        *(uint4*)(smbase + off) = make_uint4(h0, h1, h2, h3);
        *(uint4*)(smbase + MATB + off) = make_uint4(l0, l1, l2, l3);
    }
}

__global__ __launch_bounds__(256, 1) void xp_gemm_mma(const float* __restrict__ x) {
    extern __shared__ __align__(16) char sm[];
    const uint32_t sb = smem_to_u32(sm);
    const int tid = threadIdx.x;
    const int wid = tid >> 5, lane = tid & 31;
    const int wm = wid >> 1, wn = wid & 1;
    const int m0 = blockIdx.x * 128;

    float d[2][8][4];
#pragma unroll
    for (int i = 0; i < 2; i++)
#pragma unroll
        for (int j = 0; j < 8; j++)
#pragma unroll
            for (int k = 0; k < 4; k++) d[i][j][k] = 0.0f;

    // A loader coords: row = tid>>1, col-half = tid&1 (32 floats each)
    const int ar = tid >> 1, ah = tid & 1;
    const float* aptr = x + (size_t)(m0 + ar) * I_ + ah * 32;
    float4 av[8];

#define FETCHA(kt)                                                               \
    do {                                                                         \
        const float* p = aptr + (size_t)(kt) * 64;                               \
        _Pragma("unroll") for (int q = 0; q < 8; q++) av[q] = *(const float4*)(p + q * 4); \
    } while (0)

    // ---- prologue ----
    cpb(sb + 0 * STGB, tid, 0);  CP_COMMIT();
    FETCHA(0);
    cpb(sb + 1 * STGB, tid, 1);  CP_COMMIT();
    sts_a(sm + 0 * STGB, av, ar, ah);
    FETCHA(1);
    CP_WAIT1();          // group 0 (B chunk 0) complete
    __syncthreads();     // stage 0 fully visible

    const int lr = lane & 15, lc = lane >> 4;

    for (int kt = 0; kt < NKT; kt++) {
        const int s = kt & 1;
        const uint32_t aB = sb + s * STGB;
        const uint32_t bB = aB + 2 * MATB;

#pragma unroll
        for (int k16 = 0; k16 < 4; k16++) {
            uint32_t aH[2][4], aL[2][4], bH[4][4], bL[4][4];
#pragma unroll
            for (int mt = 0; mt < 2; mt++) {
                const int row = wm * 32 + mt * 16 + lr;
                const uint32_t ad = aB + row * 128 + (((2 * k16 + lc) ^ (row & 7)) * 16);
                LDSM4(aH[mt], ad);
                LDSM4(aL[mt], ad + MATB);
            }
#pragma unroll
            for (int np = 0; np < 4; np++) {
                const int row = wn * 64 + np * 16 + lr;
                const uint32_t bd = bB + row * 128 + (((2 * k16 + lc) ^ (row & 7)) * 16);
                LDSM4(bH[np], bd);
                LDSM4(bL[np], bd + MATB);
            }
#pragma unroll
            for (int mt = 0; mt < 2; mt++) {
#pragma unroll
                for (int nt = 0; nt < 8; nt++) {
                    const int np = nt >> 1, wh = nt & 1;
                    const uint32_t bh0 = wh ? bH[np][1] : bH[np][0];
                    const uint32_t bh1 = wh ? bH[np][3] : bH[np][2];
                    const uint32_t bl0 = wh ? bL[np][1] : bL[np][0];
                    const uint32_t bl1 = wh ? bL[np][3] : bL[np][2];
                    MMA16816(d[mt][nt], aH[mt], bh0, bh1);  // Ah*Bh
                    MMA16816(d[mt][nt], aH[mt], bl0, bl1);  // Ah*Bl
                    MMA16816(d[mt][nt], aL[mt], bh0, bh1);  // Al*Bh
                }
            }
        }

        if (kt + 1 < NKT) {
            sts_a(sm + (s ^ 1) * STGB, av, ar, ah);  // A(kt+1); stage s^1 free
            __syncthreads();                          // MMA(s) done + A(kt+1) visible
            if (kt + 2 < NKT) {
                cpb(sb + s * STGB, tid, kt + 2);      // B(kt+2) into stage s
                FETCHA(kt + 2);
            }
            CP_COMMIT();                              // (possibly empty) keeps counts aligned
            CP_WAIT1();                               // B(kt+1) landed
            __syncthreads();
        }
    }

    // ---- epilogue ----
    const int er = lane >> 2, ec = (lane & 3) * 2;
#pragma unroll
    for (int mt = 0; mt < 2; mt++) {
#pragma unroll
        for (int nt = 0; nt < 8; nt++) {
            const int grow = m0 + wm * 32 + mt * 16 + er;
            const int gcol = wn * 64 + nt * 8 + ec;
            *(float2*)&g_xp[(size_t)grow * H_ + gcol] = make_float2(d[mt][nt][0], d[mt][nt][1]);
            *(float2*)&g_xp[(size_t)(grow + 8) * H_ + gcol] = make_float2(d[mt][nt][2], d[mt][nt][3]);
        }
    }
#undef FETCHA
}

// =============================================================================
// Kernel 2: per-batch recurrence + FC tail + LayerNorm (unchanged, passing).
// =============================================================================
__global__ __launch_bounds__(128, 1) void rnn_tail(
    const float* __restrict__ b_ih,
    const float* __restrict__ W_hh, const float* __restrict__ b_hh,
    const float* __restrict__ W1, const float* __restrict__ b1,
    const float* __restrict__ W2, const float* __restrict__ b2,
    const float* __restrict__ gamma, const float* __restrict__ beta,
    float* __restrict__ out) {
    const int b = blockIdx.x;
    const int j = threadIdx.x;

    __shared__ __align__(16) float hbuf[2][H_];
    __shared__ float red[4];

    unsigned long long w2[64];
    const unsigned long long* wrow = (const unsigned long long*)(W_hh + j * H_);
#pragma unroll
    for (int kk = 0; kk < 64; kk++) w2[kk] = wrow[kk];
    const float bh = b_hh[j] + b_ih[j];

    hbuf[0][j] = 0.0f;
    const float* xpb = g_xp + (size_t)b * T_ * H_ + j;
    float x0 = xpb[0];
    float x1 = xpb[H_];
    __syncthreads();

    int p = 0;
    for (int t = 0; t < T_; t++) {
        const float xt = x0;
        x0 = x1;
        const int tpre = (t + 2 < T_) ? (t + 2) : (T_ - 1);
        x1 = xpb[(size_t)tpre * H_];

        const float* hb = hbuf[p];
        unsigned long long a0 = 0ull, a1 = 0ull, a2 = 0ull, a3 = 0ull;
#pragma unroll
        for (int kk = 0; kk < 32; kk += 2) {
            const float4 hA = *(const float4*)(hb + 4 * kk);
            const float4 hB = *(const float4*)(hb + 4 * kk + 4);
            a0 = ffma2(w2[2 * kk + 0], pack2(hA.x, hA.y), a0);
            a1 = ffma2(w2[2 * kk + 1], pack2(hA.z, hA.w), a1);
            a2 = ffma2(w2[2 * kk + 2], pack2(hB.x, hB.y), a2);
            a3 = ffma2(w2[2 * kk + 3], pack2(hB.z, hB.w), a3);
        }
        float s0, s1, s2, s3, s4, s5, s6, s7;
        unpack2(a0, s0, s1); unpack2(a1, s2, s3);
        unpack2(a2, s4, s5); unpack2(a3, s6, s7);
        const float s = (((s0 + s1) + (s2 + s3)) + ((s4 + s5) + (s6 + s7))) + xt + bh;

        float e;
        asm("ex2.approx.f32 %0, %1;" : "=f"(e) : "f"(s * 2.8853900817779268f));
        float r;
        asm("rcp.approx.f32 %0, %1;" : "=f"(r) : "f"(e + 1.0f));
        hbuf[p ^ 1][j] = fmaf(-2.0f, r, 1.0f);
        __syncthreads();
        p ^= 1;
    }

    float z1;
    {
        const unsigned long long* wr = (const unsigned long long*)(W1 + j * H_);
        const unsigned long long* hv = (const unsigned long long*)hbuf[p];
        unsigned long long a0 = 0ull, a1 = 0ull;
#pragma unroll
        for (int kk = 0; kk < 64; kk += 2) {
            a0 = ffma2(wr[kk], hv[kk], a0);
            a1 = ffma2(wr[kk + 1], hv[kk + 1], a1);
        }
        float l0, hh0, l1, hh1;
        unpack2(a0, l0, hh0); unpack2(a1, l1, hh1);
        z1 = fmaxf((l0 + hh0) + (l1 + hh1) + b1[j], 0.0f);
    }
    hbuf[p ^ 1][j] = z1;
    __syncthreads();

    float z2;
    {
        const unsigned long long* wr = (const unsigned long long*)(W2 + j * H_);
        const unsigned long long* hv = (const unsigned long long*)hbuf[p ^ 1];
        unsigned long long a0 = 0ull, a1 = 0ull;
#pragma unroll
        for (int kk = 0; kk < 64; kk += 2) {
            a0 = ffma2(wr[kk], hv[kk], a0);
            a1 = ffma2(wr[kk + 1], hv[kk + 1], a1);
        }
        float l0, hh0, l1, hh1;
        unpack2(a0, l0, hh0); unpack2(a1, l1, hh1);
        z2 = fmaxf((l0 + hh0) + (l1 + hh1) + b2[j], 0.0f);
    }

    float sum = z2;
#pragma unroll
    for (int o = 16; o; o >>= 1) sum += __shfl_xor_sync(0xffffffffu, sum, o);
    if ((j & 31) == 0) red[j >> 5] = sum;
    __syncthreads();
    const float mu = (red[0] + red[1] + red[2] + red[3]) * (1.0f / H_);
    const float dd = z2 - mu;
    float sq = dd * dd;
    __syncthreads();
#pragma unroll
    for (int o = 16; o; o >>= 1) sq += __shfl_xor_sync(0xffffffffu, sq, o);
    if ((j & 31) == 0) red[j >> 5] = sq;
    __syncthreads();
    const float var = (red[0] + red[1] + red[2] + red[3]) * (1.0f / H_);

    out[b * H_ + j] = gamma[j] * dd * rsqrtf(var + EPS) + beta[j];
}

// =============================================================================
extern "C" void kernel_launch(void* const* d_in, const int* in_sizes, int n_in,
                              void* d_out, int out_size) {
    const float* x     = (const float*)d_in[0];
    const float* W_ih  = (const float*)d_in[1];
    const float* b_ih  = (const float*)d_in[2];
    const float* W_hh  = (const float*)d_in[3];
    const float* b_hh  = (const float*)d_in[4];
    const float* W1    = (const float*)d_in[5];
    const float* b1    = (const float*)d_in[6];
    const float* W2    = (const float*)d_in[7];
    const float* b2    = (const float*)d_in[8];
    const float* gamma = (const float*)d_in[9];
    const float* beta  = (const float*)d_in[10];
    float* out = (float*)d_out;

    cudaFuncSetAttribute(xp_gemm_mma, cudaFuncAttributeMaxDynamicSharedMemorySize, SMTB);

    w_cvt<<<256, 256>>>(W_ih);                          // 65536 threads, 1 float4 each
    xp_gemm_mma<<<(B_ * T_) / 128, 256, SMTB>>>(x);
    rnn_tail<<<B_, H_>>>(b_ih, W_hh, b_hh, W1, b1, W2, b2, gamma, beta, out);
}